// round 10
// baseline (speedup 1.0000x reference)
#include <cuda_runtime.h>
#include <cstdint>

#define WD 128
#define HT 128
#define NB 8
#define NC 16
#define HW (HT*WD)
#define CHW (NC*HW)
#define HO 127
#define WO 127
#define TSX 16           // output tile width
#define TSY 8            // output tile height
#define PX 17            // patch width
#define PY 9             // patch height
#define NPATCH (PX*PY)   // 153
#define NUNITS (2*NPATCH)
#define NCELLS 12
#define CSTRIDE 5        // float4 stride per cell (bank-decorrelating pad)

__global__ void __launch_bounds__(256, 6) kan_tile_kernel(
    const float* __restrict__ x,
    const float* __restrict__ base_weight,
    const float* __restrict__ spline_weight,
    const float* __restrict__ spline_scaler,
    const float* __restrict__ grid,
    float* __restrict__ out)
{
    // Power-basis table: cell t (0..10): spline(u) = A + B u + C u^2 + D u^3
    // per tap (float4 over taps). Stride-5 float4 rows decorrelate banks;
    // same-cell lanes broadcast. Cell 11 = zeros. 960 B.
    __shared__ float4 tab4[NCELLS * CSTRIDE];
    // Per-channel-half tap planes for the 9x17 patch (4.9 KB).
    __shared__ float sa0[2][PY][PX];
    __shared__ float sa1[2][PY][PX];
    __shared__ float sa2[2][PY][PX];
    __shared__ float sa3[2][PY][PX];

    const int tid = threadIdx.x;

    // ── Table build: 48 threads, one float4 each ──
    if (tid < NCELLS * 4) {
        const int t = tid >> 2;
        const int k = tid & 3;
        float4 val = make_float4(0.f, 0.f, 0.f, 0.f);
        if (t <= 10) {
            float o[4];
#pragma unroll
            for (int f = 0; f < 4; f++) {
                const float sc = spline_scaler[f];
                float c[4];
#pragma unroll
                for (int jj = 0; jj < 4; jj++) {
                    const int idx = t - 3 + jj;
                    c[jj] = (idx >= 0 && idx < 8)
                          ? spline_weight[f * 8 + idx] * sc : 0.f;
                }
                float r;
                if (k == 0)      r = (c[0] + 4.f * c[1] + c[2]) * (1.f / 6.f);
                else if (k == 1) r = (c[2] - c[0]) * 0.5f;
                else if (k == 2) r = (c[0] - 2.f * c[1] + c[2]) * 0.5f;
                else             r = (3.f * (c[1] - c[2]) + c[3] - c[0]) * (1.f / 6.f);
                o[f] = r;
            }
            val = make_float4(o[0], o[1], o[2], o[3]);
        }
        tab4[t * CSTRIDE + k] = val;
    }
    __syncthreads();

    const float bw0 = __ldg(base_weight + 0);
    const float bw1 = __ldg(base_weight + 1);
    const float bw2 = __ldg(base_weight + 2);
    const float bw3 = __ldg(base_weight + 3);
    const float g0   = __ldg(grid + 0);
    const float invh = 1.0f / (__ldg(grid + 1) - g0);
    const float off0 = -g0 * invh;

    const int c0 = blockIdx.x * TSX;
    const int r0 = blockIdx.y * TSY;
    const int b  = blockIdx.z;

    // ── Eval: 153 patch pixels x 2 channel-halves = 306 units ──
#pragma unroll
    for (int e = tid; e < NUNITS; e += 256) {
        const int half = (e >= NPATCH) ? 1 : 0;
        const int p    = e - (half ? NPATCH : 0);
        const int rl = (p * 241) >> 12;       // p/17 for p <= 288
        const int cl = p - rl * PX;
        const int row = r0 + rl;
        const int col = c0 + cl;

        float a0 = 0.f, a1 = 0.f, a2 = 0.f, a3 = 0.f;
        float ssum = 0.f;

        if (row < HT && col < WD) {
            const float* xp = x + b * CHW + (half * 8) * HW + row * WD + col;
            float v[8];
#pragma unroll
            for (int q = 0; q < 8; q++)       // front-batched: MLP=8
                v[q] = __ldg(xp + q * HW);

#pragma unroll
            for (int q = 0; q < 8; q++) {
                const float vv = v[q];
                const float pp = fmaf(vv, invh, off0);
                const float fc = floorf(pp);
                const float u  = pp - fc;
                const int cell = (int)fc;
                const int cb   = ((unsigned)cell <= 10u) ? cell : 11;

                const float4* tp = tab4 + cb * CSTRIDE;
                const float4 A  = tp[0];
                const float4 Bc = tp[1];
                const float4 Cc = tp[2];
                const float4 Dc = tp[3];

                a0 += fmaf(fmaf(fmaf(Dc.x, u, Cc.x), u, Bc.x), u, A.x);
                a1 += fmaf(fmaf(fmaf(Dc.y, u, Cc.y), u, Bc.y), u, A.y);
                a2 += fmaf(fmaf(fmaf(Dc.z, u, Cc.z), u, Bc.z), u, A.z);
                a3 += fmaf(fmaf(fmaf(Dc.w, u, Cc.w), u, Bc.w), u, A.w);

                ssum += __fdividef(vv, 1.f + __expf(-vv));
            }
        }
        a0 = fmaf(ssum, bw0, a0);
        a1 = fmaf(ssum, bw1, a1);
        a2 = fmaf(ssum, bw2, a2);
        a3 = fmaf(ssum, bw3, a3);

        sa0[half][rl][cl] = a0;
        sa1[half][rl][cl] = a1;
        sa2[half][rl][cl] = a2;
        sa3[half][rl][cl] = a3;
    }

    __syncthreads();

    // ── Combine both halves + direct store (128 outputs) ──
    if (tid < TSX * TSY) {
        const int ty = tid >> 4;
        const int tx = tid & 15;
        const int r = r0 + ty;
        const int c = c0 + tx;
        if (r < HO && c < WO) {
            const float val =
                (sa0[0][ty][tx]     + sa0[1][ty][tx]) +
                (sa1[0][ty][tx + 1] + sa1[1][ty][tx + 1]) +
                (sa2[0][ty + 1][tx] + sa2[1][ty + 1][tx]) +
                (sa3[0][ty + 1][tx + 1] + sa3[1][ty + 1][tx + 1]);
            out[(b * HO + r) * WO + c] = val;
        }
    }
}

extern "C" void kernel_launch(void* const* d_in, const int* in_sizes, int n_in,
                              void* d_out, int out_size)
{
    const float* x  = (const float*)d_in[0];
    const float* bw = (const float*)d_in[1];
    const float* sw = (const float*)d_in[2];
    const float* ss = (const float*)d_in[3];
    const float* gr = (const float*)d_in[4];
    float* out = (float*)d_out;

    (void)in_sizes; (void)n_in; (void)out_size;

    dim3 gs(WD / TSX, HT / TSY, NB);   // 8 x 16 x 8 = 1024 blocks, one node
    kan_tile_kernel<<<gs, 256>>>(x, bw, sw, ss, gr, out);
}

// round 13
// speedup vs baseline: 1.1800x; 1.1800x over previous
#include <cuda_runtime.h>
#include <cstdint>

#define WD 128
#define HT 128
#define NB 8
#define NC 16
#define HW (HT*WD)
#define CHW (NC*HW)
#define HO 127
#define WO 127
#define TS 15            // output tile (15x15)
#define PS 16            // eval patch (16x16) = 256 units exactly
#define NCELLS 12

__global__ void __launch_bounds__(256) kan_tile_kernel(
    const float* __restrict__ x,
    const float* __restrict__ base_weight,
    const float* __restrict__ spline_weight,
    const float* __restrict__ spline_scaler,
    const float* __restrict__ grid,
    float* __restrict__ out)
{
    // Lane-replicated power-basis table (conflict-free):
    // cell t (0..10): spline(u) = A + B u + C u^2 + D u^3 per tap.
    // tab[(t*4 + k)*32 + lane] = float4 over taps, k in {A,B,C,D}.
    // Cell 11 = zeros (out-of-range). 24.5 KB.
    __shared__ float4 tab[NCELLS * 4 * 32];
    __shared__ float4 staging[NCELLS * 4];
    // Tap planes for the 16x16 patch (4 KB).
    __shared__ float sa0[PS][PS];
    __shared__ float sa1[PS][PS];
    __shared__ float sa2[PS][PS];
    __shared__ float sa3[PS][PS];

    const int tid = threadIdx.x;

    // ── Table build: 48 threads compute, all threads replicate ──
    if (tid < NCELLS * 4) {
        const int t = tid >> 2;
        const int k = tid & 3;
        float4 val = make_float4(0.f, 0.f, 0.f, 0.f);
        if (t <= 10) {
            float o[4];
#pragma unroll
            for (int f = 0; f < 4; f++) {
                const float sc = spline_scaler[f];
                float c[4];
#pragma unroll
                for (int jj = 0; jj < 4; jj++) {
                    const int idx = t - 3 + jj;
                    c[jj] = (idx >= 0 && idx < 8)
                          ? spline_weight[f * 8 + idx] * sc : 0.f;
                }
                float r;
                if (k == 0)      r = (c[0] + 4.f * c[1] + c[2]) * (1.f / 6.f);
                else if (k == 1) r = (c[2] - c[0]) * 0.5f;
                else if (k == 2) r = (c[0] - 2.f * c[1] + c[2]) * 0.5f;
                else             r = (3.f * (c[1] - c[2]) + c[3] - c[0]) * (1.f / 6.f);
                o[f] = r;
            }
            val = make_float4(o[0], o[1], o[2], o[3]);
        }
        staging[tid] = val;
    }
    __syncthreads();
#pragma unroll
    for (int e = tid; e < NCELLS * 4 * 32; e += 256)
        tab[e] = staging[e >> 5];
    __syncthreads();

    const float bw0 = __ldg(base_weight + 0);
    const float bw1 = __ldg(base_weight + 1);
    const float bw2 = __ldg(base_weight + 2);
    const float bw3 = __ldg(base_weight + 3);
    const float g0   = __ldg(grid + 0);
    const float invh = 1.0f / (__ldg(grid + 1) - g0);
    const float off0 = -g0 * invh;

    const int c0 = blockIdx.x * TS;
    const int r0 = blockIdx.y * TS;
    const int b  = blockIdx.z;

    // ── Eval: 16x16 patch, one unit per thread, 16 channels summed ──
    const int rl = tid >> 4;
    const int cl = tid & 15;
    const int row = r0 + rl;
    const int col = c0 + cl;

    const float4* tlane = tab + (tid & 31);   // this lane's replica column

    float a0 = 0.f, a1 = 0.f, a2 = 0.f, a3 = 0.f;
    float ssum = 0.f;

    if (row < HT && col < WD) {
        const float* xp = x + b * CHW + row * WD + col;
#pragma unroll
        for (int h = 0; h < 2; h++) {
            float v[8];
#pragma unroll
            for (int q = 0; q < 8; q++)            // front-batched: MLP=8
                v[q] = __ldg(xp + (h * 8 + q) * HW);

#pragma unroll
            for (int q = 0; q < 8; q++) {
                const float vv = v[q];
                const float pp = fmaf(vv, invh, off0);
                const float fc = floorf(pp);
                const float u  = pp - fc;
                const int cell = (int)fc;
                const int cb   = ((unsigned)cell <= 10u) ? cell : 11;

                const float4* tp = tlane + (cb << 7);   // cb*4*32
                const float4 A  = tp[0];
                const float4 Bc = tp[32];
                const float4 Cc = tp[64];
                const float4 Dc = tp[96];

                a0 += fmaf(fmaf(fmaf(Dc.x, u, Cc.x), u, Bc.x), u, A.x);
                a1 += fmaf(fmaf(fmaf(Dc.y, u, Cc.y), u, Bc.y), u, A.y);
                a2 += fmaf(fmaf(fmaf(Dc.z, u, Cc.z), u, Bc.z), u, A.z);
                a3 += fmaf(fmaf(fmaf(Dc.w, u, Cc.w), u, Bc.w), u, A.w);

                ssum += __fdividef(vv, 1.f + __expf(-vv));
            }
        }
    }
    // Base path once: a_f += ssum * bw_f
    a0 = fmaf(ssum, bw0, a0);
    a1 = fmaf(ssum, bw1, a1);
    a2 = fmaf(ssum, bw2, a2);
    a3 = fmaf(ssum, bw3, a3);

    sa0[rl][cl] = a0;
    sa1[rl][cl] = a1;
    sa2[rl][cl] = a2;
    sa3[rl][cl] = a3;

    __syncthreads();

    // ── Combine + direct store (15x15 outputs) ──
    if (rl < TS && cl < TS) {
        const int r = r0 + rl;
        const int c = c0 + cl;
        if (r < HO && c < WO) {
            const float val = sa0[rl][cl]     + sa1[rl][cl + 1] +
                              sa2[rl + 1][cl] + sa3[rl + 1][cl + 1];
            out[(b * HO + r) * WO + c] = val;
        }
    }
}

extern "C" void kernel_launch(void* const* d_in, const int* in_sizes, int n_in,
                              void* d_out, int out_size)
{
    const float* x  = (const float*)d_in[0];
    const float* bw = (const float*)d_in[1];
    const float* sw = (const float*)d_in[2];
    const float* ss = (const float*)d_in[3];
    const float* gr = (const float*)d_in[4];
    float* out = (float*)d_out;

    (void)in_sizes; (void)n_in; (void)out_size;

    dim3 gs((WO + TS - 1) / TS, (HO + TS - 1) / TS, NB);   // 9 x 9 x 8 = 648
    kan_tile_kernel<<<gs, 256>>>(x, bw, sw, ss, gr, out);
}

// round 14
// speedup vs baseline: 1.1830x; 1.0025x over previous
#include <cuda_runtime.h>
#include <cstdint>

#define WD 128
#define HT 128
#define NB 8
#define NC 16
#define HW (HT*WD)
#define CHW (NC*HW)
#define HO 127
#define WO 127
#define TS 15            // output tile (15x15)
#define PS 16            // eval patch (16x16) = 256 units exactly
#define NCELLS 12

__device__ __forceinline__ float tanh_approx(float x) {
    float r;
    asm("tanh.approx.f32 %0, %1;" : "=f"(r) : "f"(x));
    return r;
}

__global__ void __launch_bounds__(256, 4) kan_tile_kernel(
    const float* __restrict__ x,
    const float* __restrict__ base_weight,
    const float* __restrict__ spline_weight,
    const float* __restrict__ spline_scaler,
    const float* __restrict__ grid,
    float* __restrict__ out)
{
    // Lane-replicated power-basis table (conflict-free):
    // cell t (0..10): spline(u) = A + B u + C u^2 + D u^3 per tap.
    // tab[(t*4 + k)*32 + lane] = float4 over taps. Cell 11 = zeros. 24.5 KB.
    __shared__ float4 tab[NCELLS * 4 * 32];
    __shared__ float4 staging[NCELLS * 4];
    __shared__ float sa0[PS][PS];
    __shared__ float sa1[PS][PS];
    __shared__ float sa2[PS][PS];
    __shared__ float sa3[PS][PS];

    const int tid = threadIdx.x;

    // ── Table build: 48 threads compute, all replicate ──
    if (tid < NCELLS * 4) {
        const int t = tid >> 2;
        const int k = tid & 3;
        float4 val = make_float4(0.f, 0.f, 0.f, 0.f);
        if (t <= 10) {
            float o[4];
#pragma unroll
            for (int f = 0; f < 4; f++) {
                const float sc = spline_scaler[f];
                float c[4];
#pragma unroll
                for (int jj = 0; jj < 4; jj++) {
                    const int idx = t - 3 + jj;
                    c[jj] = (idx >= 0 && idx < 8)
                          ? spline_weight[f * 8 + idx] * sc : 0.f;
                }
                float r;
                if (k == 0)      r = (c[0] + 4.f * c[1] + c[2]) * (1.f / 6.f);
                else if (k == 1) r = (c[2] - c[0]) * 0.5f;
                else if (k == 2) r = (c[0] - 2.f * c[1] + c[2]) * 0.5f;
                else             r = (3.f * (c[1] - c[2]) + c[3] - c[0]) * (1.f / 6.f);
                o[f] = r;
            }
            val = make_float4(o[0], o[1], o[2], o[3]);
        }
        staging[tid] = val;
    }
    __syncthreads();
#pragma unroll
    for (int e = tid; e < NCELLS * 4 * 32; e += 256)
        tab[e] = staging[e >> 5];
    __syncthreads();

    const float bw0 = __ldg(base_weight + 0);
    const float bw1 = __ldg(base_weight + 1);
    const float bw2 = __ldg(base_weight + 2);
    const float bw3 = __ldg(base_weight + 3);
    const float g0   = __ldg(grid + 0);
    const float invh = 1.0f / (__ldg(grid + 1) - g0);
    const float off0 = -g0 * invh;

    const int c0 = blockIdx.x * TS;
    const int r0 = blockIdx.y * TS;
    const int b  = blockIdx.z;

    const int rl = tid >> 4;
    const int cl = tid & 15;
    const int row = r0 + rl;
    const int col = c0 + cl;

    const float4* tlane = tab + (tid & 31);

    // Two independent accumulator streams (break the serial chain).
    float a0A = 0.f, a1A = 0.f, a2A = 0.f, a3A = 0.f, ssA = 0.f;
    float a0B = 0.f, a1B = 0.f, a2B = 0.f, a3B = 0.f, ssB = 0.f;

    if (row < HT && col < WD) {
        const float* xp = x + b * CHW + row * WD + col;

        float v[NC];
#pragma unroll
        for (int q = 0; q < NC; q++)          // all 16 in flight (MLP=16)
            v[q] = __ldg(xp + q * HW);

#pragma unroll
        for (int q = 0; q < NC; q += 2) {
            // ── stream A: channel q ──
            {
                const float vv = v[q];
                const float pp = fmaf(vv, invh, off0);
                const float fc = floorf(pp);
                const float u  = pp - fc;
                const int cell = (int)fc;
                const int cb   = ((unsigned)cell <= 10u) ? cell : 11;
                const float4* tp = tlane + (cb << 7);
                const float4 A  = tp[0];
                const float4 Bc = tp[32];
                const float4 Cc = tp[64];
                const float4 Dc = tp[96];
                a0A += fmaf(fmaf(fmaf(Dc.x, u, Cc.x), u, Bc.x), u, A.x);
                a1A += fmaf(fmaf(fmaf(Dc.y, u, Cc.y), u, Bc.y), u, A.y);
                a2A += fmaf(fmaf(fmaf(Dc.z, u, Cc.z), u, Bc.z), u, A.z);
                a3A += fmaf(fmaf(fmaf(Dc.w, u, Cc.w), u, Bc.w), u, A.w);
                // silu(v) = 0.5 v (1 + tanh(v/2))
                const float th = tanh_approx(0.5f * vv);
                ssA = fmaf(0.5f * vv, th, fmaf(0.5f, vv, ssA));
            }
            // ── stream B: channel q+1 ──
            {
                const float vv = v[q + 1];
                const float pp = fmaf(vv, invh, off0);
                const float fc = floorf(pp);
                const float u  = pp - fc;
                const int cell = (int)fc;
                const int cb   = ((unsigned)cell <= 10u) ? cell : 11;
                const float4* tp = tlane + (cb << 7);
                const float4 A  = tp[0];
                const float4 Bc = tp[32];
                const float4 Cc = tp[64];
                const float4 Dc = tp[96];
                a0B += fmaf(fmaf(fmaf(Dc.x, u, Cc.x), u, Bc.x), u, A.x);
                a1B += fmaf(fmaf(fmaf(Dc.y, u, Cc.y), u, Bc.y), u, A.y);
                a2B += fmaf(fmaf(fmaf(Dc.z, u, Cc.z), u, Bc.z), u, A.z);
                a3B += fmaf(fmaf(fmaf(Dc.w, u, Cc.w), u, Bc.w), u, A.w);
                const float th = tanh_approx(0.5f * vv);
                ssB = fmaf(0.5f * vv, th, fmaf(0.5f, vv, ssB));
            }
        }
    }
    const float ssum = ssA + ssB;
    float a0 = fmaf(ssum, bw0, a0A + a0B);
    float a1 = fmaf(ssum, bw1, a1A + a1B);
    float a2 = fmaf(ssum, bw2, a2A + a2B);
    float a3 = fmaf(ssum, bw3, a3A + a3B);

    sa0[rl][cl] = a0;
    sa1[rl][cl] = a1;
    sa2[rl][cl] = a2;
    sa3[rl][cl] = a3;

    __syncthreads();

    // ── Combine + direct store (15x15 outputs) ──
    if (rl < TS && cl < TS) {
        const int r = r0 + rl;
        const int c = c0 + cl;
        if (r < HO && c < WO) {
            const float val = sa0[rl][cl]     + sa1[rl][cl + 1] +
                              sa2[rl + 1][cl] + sa3[rl + 1][cl + 1];
            out[(b * HO + r) * WO + c] = val;
        }
    }
}

extern "C" void kernel_launch(void* const* d_in, const int* in_sizes, int n_in,
                              void* d_out, int out_size)
{
    const float* x  = (const float*)d_in[0];
    const float* bw = (const float*)d_in[1];
    const float* sw = (const float*)d_in[2];
    const float* ss = (const float*)d_in[3];
    const float* gr = (const float*)d_in[4];
    float* out = (float*)d_out;

    (void)in_sizes; (void)n_in; (void)out_size;

    dim3 gs((WO + TS - 1) / TS, (HO + TS - 1) / TS, NB);   // 9 x 9 x 8 = 648
    kan_tile_kernel<<<gs, 256>>>(x, bw, sw, ss, gr, out);
}